// round 2
// baseline (speedup 1.0000x reference)
#include <cuda_runtime.h>

// GraphConv: out = relu( segment_sum(feature[src] -> dst) @ W^T + b )
// feature: [50000,128] f32, W: [128,128] f32, b: [128] f32, edge_index: [2,800000] i32
// out: [50000,128] f32
//
// Strategy: build CSR (dst -> list of src) on the fly, then atomic-free
// warp-per-node gather, then tiled fp32 GEMM + bias + relu.

constexpr int N_NODES = 50000;
constexpr int N_EDGES = 800000;
constexpr int D       = 128;

// ---- static scratch (no allocations allowed) ----
__device__ float g_agg[N_NODES * D];       // 25.6 MB aggregated features
__device__ int   g_deg[N_NODES];           // in-degree histogram
__device__ int   g_start[N_NODES + 1];     // CSR row offsets
__device__ int   g_cursor[N_NODES];        // fill cursors
__device__ int   g_edges[N_EDGES];         // src ids grouped by dst

// ---------------------------------------------------------------------------
// 1) zero the degree histogram
// ---------------------------------------------------------------------------
__global__ void __launch_bounds__(256) zero_deg_kernel() {
    int i = blockIdx.x * blockDim.x + threadIdx.x;
    if (i < N_NODES) g_deg[i] = 0;
}

// ---------------------------------------------------------------------------
// 2) histogram of destination nodes
// ---------------------------------------------------------------------------
__global__ void __launch_bounds__(256) hist_kernel(const int* __restrict__ ei) {
    int e = blockIdx.x * blockDim.x + threadIdx.x;
    if (e < N_EDGES) atomicAdd(&g_deg[ei[N_EDGES + e]], 1);
}

// ---------------------------------------------------------------------------
// 3) single-block exclusive prefix scan over 50k degrees
//    1024 threads, each owns a contiguous chunk; Hillis-Steele over partials.
// ---------------------------------------------------------------------------
constexpr int SCAN_T = 1024;
constexpr int CHUNK  = (N_NODES + SCAN_T - 1) / SCAN_T;   // 49

__global__ void __launch_bounds__(SCAN_T) scan_kernel() {
    __shared__ int s[SCAN_T];
    int t  = threadIdx.x;
    int lo = t * CHUNK;
    int hi = min(lo + CHUNK, N_NODES);

    int sum = 0;
    for (int i = lo; i < hi; i++) sum += g_deg[i];
    s[t] = sum;
    __syncthreads();

    // inclusive Hillis-Steele scan
    for (int off = 1; off < SCAN_T; off <<= 1) {
        int v = (t >= off) ? s[t - off] : 0;
        __syncthreads();
        s[t] += v;
        __syncthreads();
    }

    int run = (t == 0) ? 0 : s[t - 1];   // exclusive base for this chunk
    for (int i = lo; i < hi; i++) {
        g_start[i]  = run;
        g_cursor[i] = run;
        run += g_deg[i];
    }
    if (t == SCAN_T - 1) g_start[N_NODES] = N_EDGES;
}

// ---------------------------------------------------------------------------
// 4) bin fill: place src ids into CSR order
// ---------------------------------------------------------------------------
__global__ void __launch_bounds__(256) fill_kernel(const int* __restrict__ ei) {
    int e = blockIdx.x * blockDim.x + threadIdx.x;
    if (e < N_EDGES) {
        int dst = ei[N_EDGES + e];
        int src = ei[e];
        int pos = atomicAdd(&g_cursor[dst], 1);
        g_edges[pos] = src;
    }
}

// ---------------------------------------------------------------------------
// 5) gather: one warp per node, register accumulation, no atomics.
//    Each lane owns one float4 chunk of the 128-float row.
//    Unroll-4 over edges for MLP (4 independent LDG.128 in flight).
// ---------------------------------------------------------------------------
__global__ void __launch_bounds__(256) gather_kernel(const float4* __restrict__ feat4)
{
    int warp = (blockIdx.x * blockDim.x + threadIdx.x) >> 5;
    int lane = threadIdx.x & 31;
    if (warp >= N_NODES) return;

    int beg = g_start[warp];
    int end = g_start[warp + 1];

    float4 acc = make_float4(0.f, 0.f, 0.f, 0.f);

    int e = beg;
    for (; e + 4 <= end; e += 4) {
        int s0 = g_edges[e];
        int s1 = g_edges[e + 1];
        int s2 = g_edges[e + 2];
        int s3 = g_edges[e + 3];
        float4 v0 = feat4[s0 * 32 + lane];
        float4 v1 = feat4[s1 * 32 + lane];
        float4 v2 = feat4[s2 * 32 + lane];
        float4 v3 = feat4[s3 * 32 + lane];
        // pairwise to shorten the dependency chain
        float4 p, q;
        p.x = v0.x + v1.x; p.y = v0.y + v1.y; p.z = v0.z + v1.z; p.w = v0.w + v1.w;
        q.x = v2.x + v3.x; q.y = v2.y + v3.y; q.z = v2.z + v3.z; q.w = v2.w + v3.w;
        acc.x += p.x + q.x; acc.y += p.y + q.y;
        acc.z += p.z + q.z; acc.w += p.w + q.w;
    }
    for (; e < end; e++) {
        int s = g_edges[e];
        float4 v = feat4[s * 32 + lane];
        acc.x += v.x; acc.y += v.y; acc.z += v.z; acc.w += v.w;
    }

    reinterpret_cast<float4*>(g_agg)[warp * 32 + lane] = acc;
}

// ---------------------------------------------------------------------------
// 6) GEMM: out = relu( g_agg @ W^T + b )
//    BM=64, BN=128(full), BK=16, 128 threads, 8x8 register tile.
// ---------------------------------------------------------------------------
constexpr int BM = 64;
constexpr int BN = 128;
constexpr int BK = 16;

__global__ void __launch_bounds__(128) gemm_bias_relu_kernel(
    const float* __restrict__ Wm, const float* __restrict__ bias,
    float* __restrict__ out)
{
    __shared__ float As[BK][BM];   // As[k][m] = agg[m][k]
    __shared__ float Bs[BK][BN];   // Bs[k][n] = W[n][k]

    const int t  = threadIdx.x;
    const int m0 = blockIdx.x * BM;
    const int tm = (t >> 4) * 8;
    const int tn = (t & 15) * 8;

    float acc[8][8];
#pragma unroll
    for (int i = 0; i < 8; i++)
#pragma unroll
        for (int j = 0; j < 8; j++) acc[i][j] = 0.f;

    for (int k0 = 0; k0 < D; k0 += BK) {
#pragma unroll
        for (int i = 0; i < 2; i++) {
            int lin = t * 2 + i;
            int row = lin >> 2;
            int kq  = lin & 3;
            int m   = m0 + row;
            float4 v = make_float4(0.f, 0.f, 0.f, 0.f);
            if (m < N_NODES)
                v = reinterpret_cast<const float4*>(g_agg + m * D + k0)[kq];
            As[kq * 4 + 0][row] = v.x;
            As[kq * 4 + 1][row] = v.y;
            As[kq * 4 + 2][row] = v.z;
            As[kq * 4 + 3][row] = v.w;
        }
        {
            const float4* wrow = reinterpret_cast<const float4*>(Wm + t * D + k0);
#pragma unroll
            for (int q = 0; q < 4; q++) {
                float4 v = wrow[q];
                Bs[q * 4 + 0][t] = v.x;
                Bs[q * 4 + 1][t] = v.y;
                Bs[q * 4 + 2][t] = v.z;
                Bs[q * 4 + 3][t] = v.w;
            }
        }
        __syncthreads();

#pragma unroll
        for (int kk = 0; kk < BK; kk++) {
            float4 a0 = *reinterpret_cast<const float4*>(&As[kk][tm]);
            float4 a1 = *reinterpret_cast<const float4*>(&As[kk][tm + 4]);
            float4 b0 = *reinterpret_cast<const float4*>(&Bs[kk][tn]);
            float4 b1 = *reinterpret_cast<const float4*>(&Bs[kk][tn + 4]);
            float a[8]  = {a0.x, a0.y, a0.z, a0.w, a1.x, a1.y, a1.z, a1.w};
            float bb[8] = {b0.x, b0.y, b0.z, b0.w, b1.x, b1.y, b1.z, b1.w};
#pragma unroll
            for (int i = 0; i < 8; i++)
#pragma unroll
                for (int j = 0; j < 8; j++)
                    acc[i][j] = fmaf(a[i], bb[j], acc[i][j]);
        }
        __syncthreads();
    }

    float bv[8];
#pragma unroll
    for (int j = 0; j < 8; j++) bv[j] = __ldg(&bias[tn + j]);

#pragma unroll
    for (int i = 0; i < 8; i++) {
        int m = m0 + tm + i;
        if (m < N_NODES) {
            float4 r0, r1;
            r0.x = fmaxf(acc[i][0] + bv[0], 0.f);
            r0.y = fmaxf(acc[i][1] + bv[1], 0.f);
            r0.z = fmaxf(acc[i][2] + bv[2], 0.f);
            r0.w = fmaxf(acc[i][3] + bv[3], 0.f);
            r1.x = fmaxf(acc[i][4] + bv[4], 0.f);
            r1.y = fmaxf(acc[i][5] + bv[5], 0.f);
            r1.z = fmaxf(acc[i][6] + bv[6], 0.f);
            r1.w = fmaxf(acc[i][7] + bv[7], 0.f);
            float4* o = reinterpret_cast<float4*>(out + m * D + tn);
            o[0] = r0;
            o[1] = r1;
        }
    }
}

// ---------------------------------------------------------------------------
extern "C" void kernel_launch(void* const* d_in, const int* in_sizes, int n_in,
                              void* d_out, int out_size)
{
    const float* feature = (const float*)d_in[0];   // [50000,128]
    const float* Wm      = (const float*)d_in[1];   // [128,128]
    const float* bias    = (const float*)d_in[2];   // [128]
    const int*   ei      = (const int*)  d_in[3];   // [2,800000]
    float*       out     = (float*)d_out;           // [50000,128]

    (void)in_sizes; (void)n_in; (void)out_size;

    zero_deg_kernel<<<(N_NODES + 255) / 256, 256>>>();
    hist_kernel<<<(N_EDGES + 255) / 256, 256>>>(ei);
    scan_kernel<<<1, SCAN_T>>>();
    fill_kernel<<<(N_EDGES + 255) / 256, 256>>>(ei);
    {
        int total_threads = N_NODES * 32;
        gather_kernel<<<(total_threads + 255) / 256, 256>>>(
            reinterpret_cast<const float4*>(feature));
    }
    {
        int blocks = (N_NODES + BM - 1) / BM;
        gemm_bias_relu_kernel<<<blocks, 128>>>(Wm, bias, out);
    }
}

// round 3
// speedup vs baseline: 1.6089x; 1.6089x over previous
#include <cuda_runtime.h>
#include <cstdint>

// GraphConv: out = relu( segment_sum(feature[src] -> dst) @ W^T + b )
// feature: [50000,128] f32, W: [128,128] f32, b: [128] f32, edge_index: [2,800000] i32
// out: [50000,128] f32
//
// R3: atomic float4 scatter (R0 winner) + tf32 tensor-core GEMM.

constexpr int N_NODES = 50000;
constexpr int N_EDGES = 800000;
constexpr int D       = 128;

__device__ float g_agg[N_NODES * D];   // 25.6 MB scratch

// ---------------------------------------------------------------------------
// 1) zero the aggregation buffer
// ---------------------------------------------------------------------------
__global__ void __launch_bounds__(256) zero_agg_kernel() {
    int i = blockIdx.x * blockDim.x + threadIdx.x;
    if (i < N_NODES * D / 4)
        reinterpret_cast<float4*>(g_agg)[i] = make_float4(0.f, 0.f, 0.f, 0.f);
}

// ---------------------------------------------------------------------------
// 2) scatter-add  g_agg[dst] += feature[src]   (vector float4 atomics)
// ---------------------------------------------------------------------------
__global__ void __launch_bounds__(256) scatter_add_kernel(
    const float4* __restrict__ feat4, const int* __restrict__ ei)
{
    int idx = blockIdx.x * blockDim.x + threadIdx.x;
    if (idx >= N_EDGES * 32) return;
    int e = idx >> 5;
    int c = idx & 31;
    int src = __ldg(&ei[e]);
    int dst = __ldg(&ei[N_EDGES + e]);
    float4 v = feat4[src * 32 + c];
    atomicAdd(reinterpret_cast<float4*>(g_agg) + dst * 32 + c, v);
}

// ---------------------------------------------------------------------------
// 3) GEMM via tf32 mma.sync:  out = relu( g_agg @ W^T + b )
//    Block: 128 rows x 128 cols, 256 threads (8 warps).
//    Warp w owns rows [w*16, w*16+16) x all 128 cols = 16 n8-tiles.
//    K streamed in 32-wide chunks through smem (tf32-converted).
// ---------------------------------------------------------------------------
constexpr int GM = 128;   // rows per block
constexpr int CK = 32;    // K chunk
constexpr int KPAD = 36;  // padded k-stride (bank-conflict-free fragment reads)

__device__ __forceinline__ uint32_t f32_to_tf32(float f) {
    uint32_t r;
    asm volatile("cvt.rna.tf32.f32 %0, %1;" : "=r"(r) : "f"(f));
    return r;
}

__device__ __forceinline__ void mma_tf32(
    float& d0, float& d1, float& d2, float& d3,
    uint32_t a0, uint32_t a1, uint32_t a2, uint32_t a3,
    uint32_t b0, uint32_t b1)
{
    asm volatile(
        "mma.sync.aligned.m16n8k8.row.col.f32.tf32.tf32.f32 "
        "{%0,%1,%2,%3}, {%4,%5,%6,%7}, {%8,%9}, {%0,%1,%2,%3};"
        : "+f"(d0), "+f"(d1), "+f"(d2), "+f"(d3)
        : "r"(a0), "r"(a1), "r"(a2), "r"(a3), "r"(b0), "r"(b1));
}

__global__ void __launch_bounds__(256, 1) gemm_tf32_bias_relu_kernel(
    const float* __restrict__ Wm, const float* __restrict__ bias,
    float* __restrict__ out)
{
    __shared__ uint32_t As[GM * KPAD];   // As[r*KPAD + k'] = tf32(agg[m0+r][k0+k'])
    __shared__ uint32_t Bs[128 * KPAD];  // Bs[n*KPAD + k'] = tf32(W[n][k0+k'])

    const int t    = threadIdx.x;
    const int lane = t & 31;
    const int w    = t >> 5;          // warp 0..7
    const int m0   = blockIdx.x * GM;

    const int gp  = lane >> 2;        // 0..7  (group / row-in-fragment)
    const int tg  = lane & 3;         // 0..3  (thread-in-group / k-in-fragment)

    float acc[16][4];
#pragma unroll
    for (int nt = 0; nt < 16; nt++)
#pragma unroll
        for (int j = 0; j < 4; j++) acc[nt][j] = 0.f;

    for (int k0 = 0; k0 < D; k0 += CK) {
        // ---- stage A chunk: 128 rows x 32 k  (4 float4 per thread) ----
#pragma unroll
        for (int i = 0; i < 4; i++) {
            int lin = t + i * 256;          // 0..1023
            int row = lin >> 3;             // 0..127
            int q   = lin & 7;              // float4 index in 32-wide chunk
            int m   = m0 + row;
            float4 v = make_float4(0.f, 0.f, 0.f, 0.f);
            if (m < N_NODES)
                v = *reinterpret_cast<const float4*>(g_agg + m * D + k0 + q * 4);
            uint32_t* dstp = &As[row * KPAD + q * 4];
            dstp[0] = f32_to_tf32(v.x);
            dstp[1] = f32_to_tf32(v.y);
            dstp[2] = f32_to_tf32(v.z);
            dstp[3] = f32_to_tf32(v.w);
        }
        // ---- stage W chunk: 128 n x 32 k ----
#pragma unroll
        for (int i = 0; i < 4; i++) {
            int lin = t + i * 256;
            int n   = lin >> 3;
            int q   = lin & 7;
            float4 v = *reinterpret_cast<const float4*>(Wm + n * D + k0 + q * 4);
            uint32_t* dstp = &Bs[n * KPAD + q * 4];
            dstp[0] = f32_to_tf32(v.x);
            dstp[1] = f32_to_tf32(v.y);
            dstp[2] = f32_to_tf32(v.z);
            dstp[3] = f32_to_tf32(v.w);
        }
        __syncthreads();

        // ---- 4 k8-steps over the chunk ----
#pragma unroll
        for (int kk = 0; kk < 4; kk++) {
            int kb = kk * 8;
            int ar = w * 16 + gp;           // fragment rows ar, ar+8
            uint32_t a0 = As[(ar    ) * KPAD + kb + tg    ];
            uint32_t a1 = As[(ar + 8) * KPAD + kb + tg    ];
            uint32_t a2 = As[(ar    ) * KPAD + kb + tg + 4];
            uint32_t a3 = As[(ar + 8) * KPAD + kb + tg + 4];
#pragma unroll
            for (int nt = 0; nt < 16; nt++) {
                int n = nt * 8 + gp;
                uint32_t b0 = Bs[n * KPAD + kb + tg    ];
                uint32_t b1 = Bs[n * KPAD + kb + tg + 4];
                mma_tf32(acc[nt][0], acc[nt][1], acc[nt][2], acc[nt][3],
                         a0, a1, a2, a3, b0, b1);
            }
        }
        __syncthreads();
    }

    // ---- epilogue: + bias, relu, store (float2 per fragment half) ----
    int r0 = m0 + w * 16 + gp;      // rows r0, r0+8
#pragma unroll
    for (int nt = 0; nt < 16; nt++) {
        int c = nt * 8 + tg * 2;
        float b0 = __ldg(&bias[c]);
        float b1 = __ldg(&bias[c + 1]);
        if (r0 < N_NODES) {
            float2 v;
            v.x = fmaxf(acc[nt][0] + b0, 0.f);
            v.y = fmaxf(acc[nt][1] + b1, 0.f);
            *reinterpret_cast<float2*>(out + r0 * D + c) = v;
        }
        if (r0 + 8 < N_NODES) {
            float2 v;
            v.x = fmaxf(acc[nt][2] + b0, 0.f);
            v.y = fmaxf(acc[nt][3] + b1, 0.f);
            *reinterpret_cast<float2*>(out + (r0 + 8) * D + c) = v;
        }
    }
}

// ---------------------------------------------------------------------------
extern "C" void kernel_launch(void* const* d_in, const int* in_sizes, int n_in,
                              void* d_out, int out_size)
{
    const float* feature = (const float*)d_in[0];   // [50000,128]
    const float* Wm      = (const float*)d_in[1];   // [128,128]
    const float* bias    = (const float*)d_in[2];   // [128]
    const int*   ei      = (const int*)  d_in[3];   // [2,800000]
    float*       out     = (float*)d_out;           // [50000,128]

    (void)in_sizes; (void)n_in; (void)out_size;

    {
        int n = N_NODES * D / 4;
        zero_agg_kernel<<<(n + 255) / 256, 256>>>();
    }
    {
        long long total = (long long)N_EDGES * 32;
        int blocks = (int)((total + 255) / 256);
        scatter_add_kernel<<<blocks, 256>>>(
            reinterpret_cast<const float4*>(feature), ei);
    }
    {
        int blocks = (N_NODES + GM - 1) / GM;   // 391
        gemm_tf32_bias_relu_kernel<<<blocks, 256>>>(Wm, bias, out);
    }
}

// round 4
// speedup vs baseline: 2.5830x; 1.6055x over previous
#include <cuda_runtime.h>
#include <cstdint>

// GraphConv: out = relu( segment_sum(feature[src] -> dst) @ W^T + b )
// R4: capacity-binned CSR (no scan) + atomic-free warp gather + tf32 MMA GEMM.

constexpr int N_NODES = 50000;
constexpr int N_EDGES = 800000;
constexpr int D       = 128;
constexpr int CAP     = 128;          // per-node bin capacity (Poisson(16) max ~45)
constexpr int OVF_CAP = 4096;         // overflow safety net (expected: 0 used)

// ---- static scratch ----
__device__ float g_agg[N_NODES * D];          // 25.6 MB
__device__ int   g_bins[N_NODES * CAP];       // 25.6 MB binned src ids
__device__ int   g_cursor[N_NODES];           // per-node fill cursor == degree
__device__ int   g_ovf_cnt;
__device__ int2  g_ovf[OVF_CAP];              // (src,dst) overflow edges

// ---------------------------------------------------------------------------
// 1) zero cursors + overflow counter
// ---------------------------------------------------------------------------
__global__ void __launch_bounds__(256) zero_cursor_kernel() {
    int i = blockIdx.x * blockDim.x + threadIdx.x;
    if (i < N_NODES) g_cursor[i] = 0;
    if (i == 0) g_ovf_cnt = 0;
}

// ---------------------------------------------------------------------------
// 2) bin fill: g_bins[dst*CAP + pos] = src   (hist merged into cursor)
// ---------------------------------------------------------------------------
__global__ void __launch_bounds__(256) fill_kernel(const int* __restrict__ ei) {
    int e = blockIdx.x * blockDim.x + threadIdx.x;
    if (e >= N_EDGES) return;
    int src = __ldg(&ei[e]);
    int dst = __ldg(&ei[N_EDGES + e]);
    int pos = atomicAdd(&g_cursor[dst], 1);
    if (pos < CAP) {
        g_bins[dst * CAP + pos] = src;
    } else {
        int o = atomicAdd(&g_ovf_cnt, 1);
        if (o < OVF_CAP) g_ovf[o] = make_int2(src, dst);
    }
}

// ---------------------------------------------------------------------------
// 3) gather: one warp per node, lane = float4 chunk, register accumulation.
// ---------------------------------------------------------------------------
__global__ void __launch_bounds__(256) gather_kernel(const float4* __restrict__ feat4)
{
    int warp = (blockIdx.x * blockDim.x + threadIdx.x) >> 5;
    int lane = threadIdx.x & 31;
    if (warp >= N_NODES) return;

    int deg = g_cursor[warp];
    if (deg > CAP) deg = CAP;           // overflow edges handled separately
    const int* bin = &g_bins[warp * CAP];

    float4 acc = make_float4(0.f, 0.f, 0.f, 0.f);

    int e = 0;
    for (; e + 4 <= deg; e += 4) {
        int s0 = bin[e];
        int s1 = bin[e + 1];
        int s2 = bin[e + 2];
        int s3 = bin[e + 3];
        float4 v0 = feat4[s0 * 32 + lane];
        float4 v1 = feat4[s1 * 32 + lane];
        float4 v2 = feat4[s2 * 32 + lane];
        float4 v3 = feat4[s3 * 32 + lane];
        float4 p, q;
        p.x = v0.x + v1.x; p.y = v0.y + v1.y; p.z = v0.z + v1.z; p.w = v0.w + v1.w;
        q.x = v2.x + v3.x; q.y = v2.y + v3.y; q.z = v2.z + v3.z; q.w = v2.w + v3.w;
        acc.x += p.x + q.x; acc.y += p.y + q.y;
        acc.z += p.z + q.z; acc.w += p.w + q.w;
    }
    for (; e < deg; e++) {
        int s = bin[e];
        float4 v = feat4[s * 32 + lane];
        acc.x += v.x; acc.y += v.y; acc.z += v.z; acc.w += v.w;
    }

    reinterpret_cast<float4*>(g_agg)[warp * 32 + lane] = acc;
}

// ---------------------------------------------------------------------------
// 4) overflow fixup (expected empty): atomic add remaining edges
// ---------------------------------------------------------------------------
__global__ void __launch_bounds__(256) overflow_kernel(const float4* __restrict__ feat4)
{
    int cnt = g_ovf_cnt;
    if (cnt > OVF_CAP) cnt = OVF_CAP;
    int warp = threadIdx.x >> 5;     // 8 warps, single block
    int lane = threadIdx.x & 31;
    for (int i = warp; i < cnt; i += 8) {
        int2 sd = g_ovf[i];
        float4 v = feat4[sd.x * 32 + lane];
        atomicAdd(reinterpret_cast<float4*>(g_agg) + sd.y * 32 + lane, v);
    }
}

// ---------------------------------------------------------------------------
// 5) GEMM via tf32 mma.sync:  out = relu( g_agg @ W^T + b )
// ---------------------------------------------------------------------------
constexpr int GM = 128;
constexpr int CK = 32;
constexpr int KPAD = 36;

__device__ __forceinline__ uint32_t f32_to_tf32(float f) {
    uint32_t r;
    asm volatile("cvt.rna.tf32.f32 %0, %1;" : "=r"(r) : "f"(f));
    return r;
}

__device__ __forceinline__ void mma_tf32(
    float& d0, float& d1, float& d2, float& d3,
    uint32_t a0, uint32_t a1, uint32_t a2, uint32_t a3,
    uint32_t b0, uint32_t b1)
{
    asm volatile(
        "mma.sync.aligned.m16n8k8.row.col.f32.tf32.tf32.f32 "
        "{%0,%1,%2,%3}, {%4,%5,%6,%7}, {%8,%9}, {%0,%1,%2,%3};"
        : "+f"(d0), "+f"(d1), "+f"(d2), "+f"(d3)
        : "r"(a0), "r"(a1), "r"(a2), "r"(a3), "r"(b0), "r"(b1));
}

__global__ void __launch_bounds__(256, 1) gemm_tf32_bias_relu_kernel(
    const float* __restrict__ Wm, const float* __restrict__ bias,
    float* __restrict__ out)
{
    __shared__ uint32_t As[GM * KPAD];
    __shared__ uint32_t Bs[128 * KPAD];

    const int t    = threadIdx.x;
    const int lane = t & 31;
    const int w    = t >> 5;
    const int m0   = blockIdx.x * GM;

    const int gp  = lane >> 2;
    const int tg  = lane & 3;

    float acc[16][4];
#pragma unroll
    for (int nt = 0; nt < 16; nt++)
#pragma unroll
        for (int j = 0; j < 4; j++) acc[nt][j] = 0.f;

    for (int k0 = 0; k0 < D; k0 += CK) {
#pragma unroll
        for (int i = 0; i < 4; i++) {
            int lin = t + i * 256;
            int row = lin >> 3;
            int q   = lin & 7;
            int m   = m0 + row;
            float4 v = make_float4(0.f, 0.f, 0.f, 0.f);
            if (m < N_NODES)
                v = *reinterpret_cast<const float4*>(g_agg + m * D + k0 + q * 4);
            uint32_t* dstp = &As[row * KPAD + q * 4];
            dstp[0] = f32_to_tf32(v.x);
            dstp[1] = f32_to_tf32(v.y);
            dstp[2] = f32_to_tf32(v.z);
            dstp[3] = f32_to_tf32(v.w);
        }
#pragma unroll
        for (int i = 0; i < 4; i++) {
            int lin = t + i * 256;
            int n   = lin >> 3;
            int q   = lin & 7;
            float4 v = *reinterpret_cast<const float4*>(Wm + n * D + k0 + q * 4);
            uint32_t* dstp = &Bs[n * KPAD + q * 4];
            dstp[0] = f32_to_tf32(v.x);
            dstp[1] = f32_to_tf32(v.y);
            dstp[2] = f32_to_tf32(v.z);
            dstp[3] = f32_to_tf32(v.w);
        }
        __syncthreads();

#pragma unroll
        for (int kk = 0; kk < 4; kk++) {
            int kb = kk * 8;
            int ar = w * 16 + gp;
            uint32_t a0 = As[(ar    ) * KPAD + kb + tg    ];
            uint32_t a1 = As[(ar + 8) * KPAD + kb + tg    ];
            uint32_t a2 = As[(ar    ) * KPAD + kb + tg + 4];
            uint32_t a3 = As[(ar + 8) * KPAD + kb + tg + 4];
#pragma unroll
            for (int nt = 0; nt < 16; nt++) {
                int n = nt * 8 + gp;
                uint32_t b0 = Bs[n * KPAD + kb + tg    ];
                uint32_t b1 = Bs[n * KPAD + kb + tg + 4];
                mma_tf32(acc[nt][0], acc[nt][1], acc[nt][2], acc[nt][3],
                         a0, a1, a2, a3, b0, b1);
            }
        }
        __syncthreads();
    }

    int r0 = m0 + w * 16 + gp;
#pragma unroll
    for (int nt = 0; nt < 16; nt++) {
        int c = nt * 8 + tg * 2;
        float b0 = __ldg(&bias[c]);
        float b1 = __ldg(&bias[c + 1]);
        if (r0 < N_NODES) {
            float2 v;
            v.x = fmaxf(acc[nt][0] + b0, 0.f);
            v.y = fmaxf(acc[nt][1] + b1, 0.f);
            *reinterpret_cast<float2*>(out + r0 * D + c) = v;
        }
        if (r0 + 8 < N_NODES) {
            float2 v;
            v.x = fmaxf(acc[nt][2] + b0, 0.f);
            v.y = fmaxf(acc[nt][3] + b1, 0.f);
            *reinterpret_cast<float2*>(out + (r0 + 8) * D + c) = v;
        }
    }
}

// ---------------------------------------------------------------------------
extern "C" void kernel_launch(void* const* d_in, const int* in_sizes, int n_in,
                              void* d_out, int out_size)
{
    const float* feature = (const float*)d_in[0];   // [50000,128]
    const float* Wm      = (const float*)d_in[1];   // [128,128]
    const float* bias    = (const float*)d_in[2];   // [128]
    const int*   ei      = (const int*)  d_in[3];   // [2,800000]
    float*       out     = (float*)d_out;           // [50000,128]

    (void)in_sizes; (void)n_in; (void)out_size;

    zero_cursor_kernel<<<(N_NODES + 255) / 256, 256>>>();
    fill_kernel<<<(N_EDGES + 255) / 256, 256>>>(ei);
    {
        int total_threads = N_NODES * 32;
        gather_kernel<<<(total_threads + 255) / 256, 256>>>(
            reinterpret_cast<const float4*>(feature));
    }
    overflow_kernel<<<1, 256>>>(reinterpret_cast<const float4*>(feature));
    {
        int blocks = (N_NODES + GM - 1) / GM;
        gemm_tf32_bias_relu_kernel<<<blocks, 256>>>(Wm, bias, out);
    }
}